// round 9
// baseline (speedup 1.0000x reference)
#include <cuda_runtime.h>
#include <cuda_fp16.h>

#define NA 4096
#define H  64
#define OD 48
#define NSEG 48
#define PC (NSEG * OD)    /* 2304 logical cols */
#define PCP (NSEG * 64)   /* 3072 padded cols: 128B per segment */
#define PROWB 6144u       /* bytes per padded fp16 P row */

// Scratch (device globals: allocation-free rule). Tail pad: sentinel (s=48)
// on the last row reads the first 96B past the array.
__device__ __align__(128) __half g_P[(size_t)NA * PCP + 64];  // 25.2 MB
__device__ float         g_Wt[H * PC];               // 589 KB reshaped weights
__device__ unsigned char g_seg[(size_t)NA * NA];     // 16.7 MB seg ids
__device__ float         g_invc[NA * 64];            // 1/count per (i,s), 0-pad

// ---------------------------------------------------------------------------
// Wt[k][s*48+o] = fc_w[o, s*64+k];  also zero the g_P tail pad.
// ---------------------------------------------------------------------------
__global__ void k_reshape(const float* __restrict__ fw) {
    int idx = blockIdx.x * blockDim.x + threadIdx.x;
    if (idx < 64) g_P[(size_t)NA * PCP + idx] = __float2half(0.f);
    if (idx >= H * PC) return;
    int k = idx / PC, c = idx - k * PC;
    int s = c / OD, o = c - s * OD;
    g_Wt[idx] = fw[o * (NSEG * H) + s * H + k];
}

// ---------------------------------------------------------------------------
// P[j][s*64+o] = sum_k hidden[j][k] * Wt[k][s*48+o]  (padded store layout)
// ---------------------------------------------------------------------------
#define GR 8
__global__ __launch_bounds__(256) void k_gemmP(const float* __restrict__ hidden) {
    __shared__ float sh[GR][H];
    int t = threadIdx.x;
    int jb = blockIdx.x * GR;
    for (int idx = t; idx < GR * H; idx += 256)
        sh[idx >> 6][idx & 63] = hidden[jb * H + idx];
    __syncthreads();

    // padded column offsets for this thread's 9 logical columns
    int poff[9];
#pragma unroll
    for (int u = 0; u < 9; u++) {
        int col = u * 256 + t;
        int s = col / OD, o = col - s * OD;
        poff[u] = s * 64 + o;
    }

    float acc[GR][9];
#pragma unroll
    for (int j = 0; j < GR; j++)
#pragma unroll
        for (int u = 0; u < 9; u++) acc[j][u] = 0.f;

    for (int k = 0; k < H; k++) {
        float w[9];
#pragma unroll
        for (int u = 0; u < 9; u++) w[u] = g_Wt[k * PC + u * 256 + t];
#pragma unroll
        for (int j = 0; j < GR; j++) {
            float hv = sh[j][k];
#pragma unroll
            for (int u = 0; u < 9; u++) acc[j][u] = fmaf(hv, w[u], acc[j][u]);
        }
    }
#pragma unroll
    for (int j = 0; j < GR; j++)
#pragma unroll
        for (int u = 0; u < 9; u++)
            g_P[(size_t)(jb + j) * PCP + poff[u]] = __float2half_rn(acc[j][u]);
}

// ---------------------------------------------------------------------------
// seg(i,j): MUFU-free (ring via r^2 thresholds, wedge via octant compares,
// exactly replicating trunc(atan2*4/pi + 3) mod 8). 48 = invalid sentinel.
// ---------------------------------------------------------------------------
__device__ __forceinline__ int seg_of(float xi, float yi, float xj, float yj) {
    float dx = xj - xi, dy = yj - yi;
    float r2 = fmaf(dx, dx, dy * dy);
    if (r2 < 0.25f)          return NSEG;
    if (r2 >= 36.75834735f)  return NSEG;
    int ring = (r2 >= 0.574349177f) + (r2 >= 1.319507911f) + (r2 >= 3.031433132f)
             + (r2 >= 6.964404507f) + (r2 >= 16.0f);
    int w;
    if (dy > 0.f) {
        if (dx > 0.f)      w = (dy <  dx) ? 3 : 4;
        else if (dx < 0.f) w = (dy > -dx) ? 5 : 6;
        else               w = 5;
    } else if (dy < 0.f) {
        if (dx > 0.f)      w = (-dy <= dx) ? 2 : 1;
        else if (dx < 0.f) w = 0;
        else               w = 1;
    } else {
        w = (dx >= 0.f) ? 3 : 7;
    }
    return ring * 8 + w;
}

// ---------------------------------------------------------------------------
// k_seg: warp per i. Computes g_seg[i][j] (u8) and g_invc[i][s] (1/count).
// ---------------------------------------------------------------------------
__global__ __launch_bounds__(256) void k_seg(const float2* __restrict__ yp) {
    __shared__ unsigned short hist[8][48 * 33];
    int wp = threadIdx.x >> 5, lane = threadIdx.x & 31;
    int i = blockIdx.x * 8 + wp;
    float2 pi = yp[i];

    for (int idx = lane; idx < 48 * 33; idx += 32) hist[wp][idx] = 0;
    __syncwarp();

    unsigned char* segrow = g_seg + (size_t)i * NA;
    for (int base = 0; base < NA; base += 32) {
        float2 pj = yp[base + lane];
        int s = seg_of(pi.x, pi.y, pj.x, pj.y);
        segrow[base + lane] = (unsigned char)s;
        if (s < NSEG) hist[wp][s * 33 + lane]++;
    }
    __syncwarp();
    for (int s = lane; s < 64; s += 32) {
        float w = 0.f;
        if (s < NSEG) {
            unsigned c = 0;
#pragma unroll
            for (int k = 0; k < 32; k++) c += hist[wp][s * 33 + k];
            w = (c > 0) ? (1.0f / (float)c) : 0.0f;
        }
        g_invc[i * 64 + s] = w;
    }
}

// ---------------------------------------------------------------------------
// k_main: warp per i. 4 pairs per LDG.128 iteration:
//   lanes 0-23 = 4 groups of 6, group g handles pair 4t+g, lane sub owns
//   outputs sub*8..sub*8+7 (one 16B load = one 128B line per pair).
//   Lanes 24-31 mirror group 0's lines (unpredicated, no extra wavefronts).
// Combine: shfl_down(+6) then (+12) sums groups 0..3 into lanes 0-5.
// ---------------------------------------------------------------------------
__global__ __launch_bounds__(256) void k_main(const float* __restrict__ fb,
                                              float* __restrict__ out) {
    __shared__ float         wtab[8][64];
    __shared__ unsigned char segbuf[8][1024];
    int wp = threadIdx.x >> 5, lane = threadIdx.x & 31;
    int i = blockIdx.x * 8 + wp;

    for (int s = lane; s < 64; s += 32) wtab[wp][s] = g_invc[i * 64 + s];
    __syncwarp();

    int grp = (lane < 24) ? (lane / 6) : 0;          // pair group 0..3
    int sub = (lane < 24) ? (lane - grp * 6) : ((lane - 24) % 6);  // 0..5
    const unsigned char* Pb = (const unsigned char*)g_P + (unsigned)(sub * 16);

    float a0 = 0.f, a1 = 0.f, a2 = 0.f, a3 = 0.f;
    float a4 = 0.f, a5 = 0.f, a6 = 0.f, a7 = 0.f;
    const unsigned char* segrow = g_seg + (size_t)i * NA;

    for (int c0 = 0; c0 < NA; c0 += 1024) {
        const uint4* src = (const uint4*)(segrow + c0);
        uint4* dst = (uint4*)segbuf[wp];
        dst[lane]      = src[lane];
        dst[lane + 32] = src[lane + 32];
        __syncwarp();

        const unsigned char* rp = Pb + (size_t)c0 * PROWB;
#pragma unroll 4
        for (int t = 0; t < 256; t++) {
            int p = 4 * t + grp;                      // chunk-local pair
            int s = segbuf[wp][p];                    // LDS.U8 (<=4 words)
            float w = wtab[wp][s];                    // LDS (<=4 banks)
            const uint4* q = (const uint4*)(rp + (unsigned)p * PROWB
                                               + ((unsigned)s << 7));
            uint4 v = *q;                             // 1 line per pair
            float2 f0 = __half22float2(*(const __half2*)&v.x);
            float2 f1 = __half22float2(*(const __half2*)&v.y);
            float2 f2 = __half22float2(*(const __half2*)&v.z);
            float2 f3 = __half22float2(*(const __half2*)&v.w);
            a0 = fmaf(w, f0.x, a0); a1 = fmaf(w, f0.y, a1);
            a2 = fmaf(w, f1.x, a2); a3 = fmaf(w, f1.y, a3);
            a4 = fmaf(w, f2.x, a4); a5 = fmaf(w, f2.y, a5);
            a6 = fmaf(w, f3.x, a6); a7 = fmaf(w, f3.y, a7);
        }
        __syncwarp();
    }

    // combine 4 groups: round 1 (+6) -> g0+=g1, g2+=g3; round 2 (+12)
#pragma unroll
    for (int d = 6; d <= 12; d += 6) {
        a0 += __shfl_down_sync(0xffffffffu, a0, d);
        a1 += __shfl_down_sync(0xffffffffu, a1, d);
        a2 += __shfl_down_sync(0xffffffffu, a2, d);
        a3 += __shfl_down_sync(0xffffffffu, a3, d);
        a4 += __shfl_down_sync(0xffffffffu, a4, d);
        a5 += __shfl_down_sync(0xffffffffu, a5, d);
        a6 += __shfl_down_sync(0xffffffffu, a6, d);
        a7 += __shfl_down_sync(0xffffffffu, a7, d);
    }

    if (lane < 6) {
        const float4 b0 = ((const float4*)fb)[2 * lane];
        const float4 b1 = ((const float4*)fb)[2 * lane + 1];
        float4 r0, r1;
        r0.x = fmaxf(a0 + b0.x, 0.f); r0.y = fmaxf(a1 + b0.y, 0.f);
        r0.z = fmaxf(a2 + b0.z, 0.f); r0.w = fmaxf(a3 + b0.w, 0.f);
        r1.x = fmaxf(a4 + b1.x, 0.f); r1.y = fmaxf(a5 + b1.y, 0.f);
        r1.z = fmaxf(a6 + b1.z, 0.f); r1.w = fmaxf(a7 + b1.w, 0.f);
        float* op = out + i * OD + lane * 8;
        *(float4*)op       = r0;
        *(float4*)(op + 4) = r1;
    }
}

// ---------------------------------------------------------------------------
extern "C" void kernel_launch(void* const* d_in, const int* in_sizes, int n_in,
                              void* d_out, int out_size) {
    const float* ypred  = (const float*)d_in[0];
    const float* hidden = (const float*)d_in[1];
    const float* fc_w   = (const float*)d_in[2];
    const float* fc_b   = (const float*)d_in[3];
    float* out = (float*)d_out;

    k_reshape<<<(H * PC + 255) / 256, 256>>>(fc_w);
    k_gemmP<<<NA / GR, 256>>>(hidden);
    k_seg<<<NA / 8, 256>>>((const float2*)ypred);
    k_main<<<NA / 8, 256>>>(fc_b, out);
}

// round 10
// speedup vs baseline: 1.3077x; 1.3077x over previous
#include <cuda_runtime.h>
#include <cuda_fp16.h>

#define NA 4096
#define H  64
#define OD 48
#define NSEG 48
#define PC (NSEG * OD)    /* 2304 logical cols */
#define PCP (NSEG * 64)   /* 3072 padded cols: 128B per segment */
#define PROWB 6144u       /* bytes per padded fp16 P row */

// Scratch (device globals: allocation-free rule). Tail pad: sentinel (s=48)
// on the last row reads the first 96B past the array.
__device__ __align__(128) __half g_P[(size_t)NA * PCP + 64];  // 25.2 MB
__device__ float         g_Wt[H * PC];               // 589 KB reshaped weights
__device__ unsigned char g_seg[(size_t)NA * NA];     // 16.7 MB seg ids
__device__ float         g_invc[NA * 64];            // 1/count per (i,s), 0-pad

// ---------------------------------------------------------------------------
// Wt[k][s*48+o] = fc_w[o, s*64+k];  also zero the g_P tail pad.
// ---------------------------------------------------------------------------
__global__ void k_reshape(const float* __restrict__ fw) {
    int idx = blockIdx.x * blockDim.x + threadIdx.x;
    if (idx < 64) g_P[(size_t)NA * PCP + idx] = __float2half(0.f);
    if (idx >= H * PC) return;
    int k = idx / PC, c = idx - k * PC;
    int s = c / OD, o = c - s * OD;
    g_Wt[idx] = fw[o * (NSEG * H) + s * H + k];
}

// ---------------------------------------------------------------------------
// P[j][s*64+o] = sum_k hidden[j][k] * Wt[k][s*48+o]  (padded store layout)
// ---------------------------------------------------------------------------
#define GR 8
__global__ __launch_bounds__(256) void k_gemmP(const float* __restrict__ hidden) {
    __shared__ float sh[GR][H];
    int t = threadIdx.x;
    int jb = blockIdx.x * GR;
    for (int idx = t; idx < GR * H; idx += 256)
        sh[idx >> 6][idx & 63] = hidden[jb * H + idx];
    __syncthreads();

    int poff[9];
#pragma unroll
    for (int u = 0; u < 9; u++) {
        int col = u * 256 + t;
        int s = col / OD, o = col - s * OD;
        poff[u] = s * 64 + o;
    }

    float acc[GR][9];
#pragma unroll
    for (int j = 0; j < GR; j++)
#pragma unroll
        for (int u = 0; u < 9; u++) acc[j][u] = 0.f;

    for (int k = 0; k < H; k++) {
        float w[9];
#pragma unroll
        for (int u = 0; u < 9; u++) w[u] = g_Wt[k * PC + u * 256 + t];
#pragma unroll
        for (int j = 0; j < GR; j++) {
            float hv = sh[j][k];
#pragma unroll
            for (int u = 0; u < 9; u++) acc[j][u] = fmaf(hv, w[u], acc[j][u]);
        }
    }
#pragma unroll
    for (int j = 0; j < GR; j++)
#pragma unroll
        for (int u = 0; u < 9; u++)
            g_P[(size_t)(jb + j) * PCP + poff[u]] = __float2half_rn(acc[j][u]);
}

// ---------------------------------------------------------------------------
// seg(i,j): MUFU-free (ring via r^2 thresholds, wedge via octant compares,
// exactly replicating trunc(atan2*4/pi + 3) mod 8). 48 = invalid sentinel.
// ---------------------------------------------------------------------------
__device__ __forceinline__ int seg_of(float xi, float yi, float xj, float yj) {
    float dx = xj - xi, dy = yj - yi;
    float r2 = fmaf(dx, dx, dy * dy);
    if (r2 < 0.25f)          return NSEG;
    if (r2 >= 36.75834735f)  return NSEG;
    int ring = (r2 >= 0.574349177f) + (r2 >= 1.319507911f) + (r2 >= 3.031433132f)
             + (r2 >= 6.964404507f) + (r2 >= 16.0f);
    int w;
    if (dy > 0.f) {
        if (dx > 0.f)      w = (dy <  dx) ? 3 : 4;
        else if (dx < 0.f) w = (dy > -dx) ? 5 : 6;
        else               w = 5;
    } else if (dy < 0.f) {
        if (dx > 0.f)      w = (-dy <= dx) ? 2 : 1;
        else if (dx < 0.f) w = 0;
        else               w = 1;
    } else {
        w = (dx >= 0.f) ? 3 : 7;
    }
    return ring * 8 + w;
}

// ---------------------------------------------------------------------------
// k_seg: warp per i. Computes g_seg[i][j] (u8) and g_invc[i][s] (1/count).
// ---------------------------------------------------------------------------
__global__ __launch_bounds__(256) void k_seg(const float2* __restrict__ yp) {
    __shared__ unsigned short hist[8][48 * 33];
    int wp = threadIdx.x >> 5, lane = threadIdx.x & 31;
    int i = blockIdx.x * 8 + wp;
    float2 pi = yp[i];

    for (int idx = lane; idx < 48 * 33; idx += 32) hist[wp][idx] = 0;
    __syncwarp();

    unsigned char* segrow = g_seg + (size_t)i * NA;
    for (int base = 0; base < NA; base += 32) {
        float2 pj = yp[base + lane];
        int s = seg_of(pi.x, pi.y, pj.x, pj.y);
        segrow[base + lane] = (unsigned char)s;
        if (s < NSEG) hist[wp][s * 33 + lane]++;
    }
    __syncwarp();
    for (int s = lane; s < 64; s += 32) {
        float w = 0.f;
        if (s < NSEG) {
            unsigned c = 0;
#pragma unroll
            for (int k = 0; k < 32; k++) c += hist[wp][s * 33 + k];
            w = (c > 0) ? (1.0f / (float)c) : 0.0f;
        }
        g_invc[i * 64 + s] = w;
    }
}

// ---------------------------------------------------------------------------
// k_main: warp per i. 4 pairs per LDG.128; batched unroll-8 (32 pairs/iter)
// with 8 loads in flight (launch_bounds(256,2) lifts the 32-reg cap that
// killed MLP in R9). Lane roles: lanes 0-23 = 4 groups of 6 (group g ->
// pair 4t+g, sub owns outs sub*8..+7); lanes 24-31 mirror group 0's lines.
// ---------------------------------------------------------------------------
#define UNR 8
__global__ __launch_bounds__(256, 2) void k_main(const float* __restrict__ fb,
                                                 float* __restrict__ out) {
    __shared__ float         wtab[8][64];
    __shared__ unsigned char segbuf[8][1024];
    int wp = threadIdx.x >> 5, lane = threadIdx.x & 31;
    int i = blockIdx.x * 8 + wp;

    for (int s = lane; s < 64; s += 32) wtab[wp][s] = g_invc[i * 64 + s];
    __syncwarp();

    int grp = (lane < 24) ? (lane / 6) : 0;
    int sub = (lane < 24) ? (lane - grp * 6) : ((lane - 24) % 6);
    const unsigned char* Pb = (const unsigned char*)g_P + (unsigned)(sub * 16);

    float a0 = 0.f, a1 = 0.f, a2 = 0.f, a3 = 0.f;
    float a4 = 0.f, a5 = 0.f, a6 = 0.f, a7 = 0.f;
    const unsigned char* segrow = g_seg + (size_t)i * NA;

    for (int c0 = 0; c0 < NA; c0 += 1024) {
        const uint4* src = (const uint4*)(segrow + c0);
        uint4* dst = (uint4*)segbuf[wp];
        dst[lane]      = src[lane];
        dst[lane + 32] = src[lane + 32];
        __syncwarp();

        const unsigned char* rp = Pb + (size_t)c0 * PROWB;
        for (int t0 = 0; t0 < 256; t0 += UNR) {
            int   sv[UNR];
            float wv[UNR];
            uint4 vv[UNR];
#pragma unroll
            for (int u = 0; u < UNR; u++)
                sv[u] = segbuf[wp][4 * (t0 + u) + grp];     // 8x LDS.U8
#pragma unroll
            for (int u = 0; u < UNR; u++)
                wv[u] = wtab[wp][sv[u]];                    // 8x LDS
#pragma unroll
            for (int u = 0; u < UNR; u++)
                vv[u] = *(const uint4*)(rp
                          + (unsigned)(4 * (t0 + u) + grp) * PROWB
                          + ((unsigned)sv[u] << 7));        // 8x LDG.128
#pragma unroll
            for (int u = 0; u < UNR; u++) {
                float w = wv[u];
                float2 f0 = __half22float2(*(const __half2*)&vv[u].x);
                float2 f1 = __half22float2(*(const __half2*)&vv[u].y);
                float2 f2 = __half22float2(*(const __half2*)&vv[u].z);
                float2 f3 = __half22float2(*(const __half2*)&vv[u].w);
                a0 = fmaf(w, f0.x, a0); a1 = fmaf(w, f0.y, a1);
                a2 = fmaf(w, f1.x, a2); a3 = fmaf(w, f1.y, a3);
                a4 = fmaf(w, f2.x, a4); a5 = fmaf(w, f2.y, a5);
                a6 = fmaf(w, f3.x, a6); a7 = fmaf(w, f3.y, a7);
            }
        }
        __syncwarp();
    }

    // combine 4 groups: round 1 (+6) -> g0+=g1, g2+=g3; round 2 (+12)
#pragma unroll
    for (int d = 6; d <= 12; d += 6) {
        a0 += __shfl_down_sync(0xffffffffu, a0, d);
        a1 += __shfl_down_sync(0xffffffffu, a1, d);
        a2 += __shfl_down_sync(0xffffffffu, a2, d);
        a3 += __shfl_down_sync(0xffffffffu, a3, d);
        a4 += __shfl_down_sync(0xffffffffu, a4, d);
        a5 += __shfl_down_sync(0xffffffffu, a5, d);
        a6 += __shfl_down_sync(0xffffffffu, a6, d);
        a7 += __shfl_down_sync(0xffffffffu, a7, d);
    }

    if (lane < 6) {
        const float4 b0 = ((const float4*)fb)[2 * lane];
        const float4 b1 = ((const float4*)fb)[2 * lane + 1];
        float4 r0, r1;
        r0.x = fmaxf(a0 + b0.x, 0.f); r0.y = fmaxf(a1 + b0.y, 0.f);
        r0.z = fmaxf(a2 + b0.z, 0.f); r0.w = fmaxf(a3 + b0.w, 0.f);
        r1.x = fmaxf(a4 + b1.x, 0.f); r1.y = fmaxf(a5 + b1.y, 0.f);
        r1.z = fmaxf(a6 + b1.z, 0.f); r1.w = fmaxf(a7 + b1.w, 0.f);
        float* op = out + i * OD + lane * 8;
        *(float4*)op       = r0;
        *(float4*)(op + 4) = r1;
    }
}

// ---------------------------------------------------------------------------
extern "C" void kernel_launch(void* const* d_in, const int* in_sizes, int n_in,
                              void* d_out, int out_size) {
    const float* ypred  = (const float*)d_in[0];
    const float* hidden = (const float*)d_in[1];
    const float* fc_w   = (const float*)d_in[2];
    const float* fc_b   = (const float*)d_in[3];
    float* out = (float*)d_out;

    k_reshape<<<(H * PC + 255) / 256, 256>>>(fc_w);
    k_gemmP<<<NA / GR, 256>>>(hidden);
    k_seg<<<NA / 8, 256>>>((const float2*)ypred);
    k_main<<<NA / 8, 256>>>(fc_b, out);
}

// round 11
// speedup vs baseline: 1.4078x; 1.0766x over previous
#include <cuda_runtime.h>
#include <cuda_fp16.h>

#define NA 4096
#define H  64
#define OD 48
#define NSEG 48
#define PC (NSEG * OD)    /* 2304 logical cols */
#define PCP (NSEG * 64)   /* 3072 padded cols: 128B per segment */
#define PROWB 6144u       /* bytes per padded fp16 P row */

// Scratch (device globals: allocation-free rule). Tail pad: sentinel (s=48)
// on the last row reads the first 96B past the array.
__device__ __align__(128) __half g_P[(size_t)NA * PCP + 64];  // 25.2 MB
__device__ float         g_Wt[H * PC];               // 589 KB reshaped weights
__device__ unsigned char g_seg[(size_t)NA * NA];     // 16.7 MB seg ids
__device__ float         g_invc[NA * 64];            // 1/count per (i,s), 0-pad

// ---------------------------------------------------------------------------
// Wt[k][s*48+o] = fc_w[o, s*64+k];  also zero the g_P tail pad.
// ---------------------------------------------------------------------------
__global__ void k_reshape(const float* __restrict__ fw) {
    int idx = blockIdx.x * blockDim.x + threadIdx.x;
    if (idx < 64) g_P[(size_t)NA * PCP + idx] = __float2half(0.f);
    if (idx >= H * PC) return;
    int k = idx / PC, c = idx - k * PC;
    int s = c / OD, o = c - s * OD;
    g_Wt[idx] = fw[o * (NSEG * H) + s * H + k];
}

// ---------------------------------------------------------------------------
// P[j][s*64+o] = sum_k hidden[j][k] * Wt[k][s*48+o]  (padded store layout)
// ---------------------------------------------------------------------------
#define GR 8
__global__ __launch_bounds__(256) void k_gemmP(const float* __restrict__ hidden) {
    __shared__ float sh[GR][H];
    int t = threadIdx.x;
    int jb = blockIdx.x * GR;
    for (int idx = t; idx < GR * H; idx += 256)
        sh[idx >> 6][idx & 63] = hidden[jb * H + idx];
    __syncthreads();

    int poff[9];
#pragma unroll
    for (int u = 0; u < 9; u++) {
        int col = u * 256 + t;
        int s = col / OD, o = col - s * OD;
        poff[u] = s * 64 + o;
    }

    float acc[GR][9];
#pragma unroll
    for (int j = 0; j < GR; j++)
#pragma unroll
        for (int u = 0; u < 9; u++) acc[j][u] = 0.f;

    for (int k = 0; k < H; k++) {
        float w[9];
#pragma unroll
        for (int u = 0; u < 9; u++) w[u] = g_Wt[k * PC + u * 256 + t];
#pragma unroll
        for (int j = 0; j < GR; j++) {
            float hv = sh[j][k];
#pragma unroll
            for (int u = 0; u < 9; u++) acc[j][u] = fmaf(hv, w[u], acc[j][u]);
        }
    }
#pragma unroll
    for (int j = 0; j < GR; j++)
#pragma unroll
        for (int u = 0; u < 9; u++)
            g_P[(size_t)(jb + j) * PCP + poff[u]] = __float2half_rn(acc[j][u]);
}

// ---------------------------------------------------------------------------
// seg(i,j): MUFU-free (ring via r^2 thresholds, wedge via octant compares,
// exactly replicating trunc(atan2*4/pi + 3) mod 8). 48 = invalid sentinel.
// ---------------------------------------------------------------------------
__device__ __forceinline__ int seg_of(float xi, float yi, float xj, float yj) {
    float dx = xj - xi, dy = yj - yi;
    float r2 = fmaf(dx, dx, dy * dy);
    if (r2 < 0.25f)          return NSEG;
    if (r2 >= 36.75834735f)  return NSEG;
    int ring = (r2 >= 0.574349177f) + (r2 >= 1.319507911f) + (r2 >= 3.031433132f)
             + (r2 >= 6.964404507f) + (r2 >= 16.0f);
    int w;
    if (dy > 0.f) {
        if (dx > 0.f)      w = (dy <  dx) ? 3 : 4;
        else if (dx < 0.f) w = (dy > -dx) ? 5 : 6;
        else               w = 5;
    } else if (dy < 0.f) {
        if (dx > 0.f)      w = (-dy <= dx) ? 2 : 1;
        else if (dx < 0.f) w = 0;
        else               w = 1;
    } else {
        w = (dx >= 0.f) ? 3 : 7;
    }
    return ring * 8 + w;
}

// ---------------------------------------------------------------------------
// k_seg: warp per i. Computes g_seg[i][j] (u8) and g_invc[i][s] (1/count).
// ---------------------------------------------------------------------------
__global__ __launch_bounds__(256) void k_seg(const float2* __restrict__ yp) {
    __shared__ unsigned short hist[8][48 * 33];
    int wp = threadIdx.x >> 5, lane = threadIdx.x & 31;
    int i = blockIdx.x * 8 + wp;
    float2 pi = yp[i];

    for (int idx = lane; idx < 48 * 33; idx += 32) hist[wp][idx] = 0;
    __syncwarp();

    unsigned char* segrow = g_seg + (size_t)i * NA;
    for (int base = 0; base < NA; base += 32) {
        float2 pj = yp[base + lane];
        int s = seg_of(pi.x, pi.y, pj.x, pj.y);
        segrow[base + lane] = (unsigned char)s;
        if (s < NSEG) hist[wp][s * 33 + lane]++;
    }
    __syncwarp();
    for (int s = lane; s < 64; s += 32) {
        float w = 0.f;
        if (s < NSEG) {
            unsigned c = 0;
#pragma unroll
            for (int k = 0; k < 32; k++) c += hist[wp][s * 33 + k];
            w = (c > 0) ? (1.0f / (float)c) : 0.0f;
        }
        g_invc[i * 64 + s] = w;
    }
}

// ---------------------------------------------------------------------------
// k_main: warp per i. 4 pairs per LDG.128; batched unroll-8 (32 pairs/iter).
// launch_bounds(256, 4): 64-reg cap -> 4 blocks/SM, single-wave 512-block
// grid (R10 ran 3/SM with a 68-block second wave = pure tail loss).
// Lane roles: lanes 0-23 = 4 groups of 6 (group g -> pair 4t+g, sub owns
// outs sub*8..+7); lanes 24-31 mirror group 0's lines (no extra sectors).
// ---------------------------------------------------------------------------
#define UNR 8
__global__ __launch_bounds__(256, 4) void k_main(const float* __restrict__ fb,
                                                 float* __restrict__ out) {
    __shared__ float         wtab[8][64];
    __shared__ unsigned char segbuf[8][1024];
    int wp = threadIdx.x >> 5, lane = threadIdx.x & 31;
    int i = blockIdx.x * 8 + wp;

    for (int s = lane; s < 64; s += 32) wtab[wp][s] = g_invc[i * 64 + s];
    __syncwarp();

    int grp = (lane < 24) ? (lane / 6) : 0;
    int sub = (lane < 24) ? (lane - grp * 6) : ((lane - 24) % 6);
    const unsigned char* Pb = (const unsigned char*)g_P + (unsigned)(sub * 16);

    float a0 = 0.f, a1 = 0.f, a2 = 0.f, a3 = 0.f;
    float a4 = 0.f, a5 = 0.f, a6 = 0.f, a7 = 0.f;
    const unsigned char* segrow = g_seg + (size_t)i * NA;

    for (int c0 = 0; c0 < NA; c0 += 1024) {
        const uint4* src = (const uint4*)(segrow + c0);
        uint4* dst = (uint4*)segbuf[wp];
        dst[lane]      = src[lane];
        dst[lane + 32] = src[lane + 32];
        __syncwarp();

        const unsigned char* rp = Pb + (size_t)c0 * PROWB;
        for (int t0 = 0; t0 < 256; t0 += UNR) {
            int   sv[UNR];
            float wv[UNR];
            uint4 vv[UNR];
#pragma unroll
            for (int u = 0; u < UNR; u++)
                sv[u] = segbuf[wp][4 * (t0 + u) + grp];     // 8x LDS.U8
#pragma unroll
            for (int u = 0; u < UNR; u++)
                wv[u] = wtab[wp][sv[u]];                    // 8x LDS
#pragma unroll
            for (int u = 0; u < UNR; u++)
                vv[u] = *(const uint4*)(rp
                          + (unsigned)(4 * (t0 + u) + grp) * PROWB
                          + ((unsigned)sv[u] << 7));        // 8x LDG.128
#pragma unroll
            for (int u = 0; u < UNR; u++) {
                float w = wv[u];
                float2 f0 = __half22float2(*(const __half2*)&vv[u].x);
                float2 f1 = __half22float2(*(const __half2*)&vv[u].y);
                float2 f2 = __half22float2(*(const __half2*)&vv[u].z);
                float2 f3 = __half22float2(*(const __half2*)&vv[u].w);
                a0 = fmaf(w, f0.x, a0); a1 = fmaf(w, f0.y, a1);
                a2 = fmaf(w, f1.x, a2); a3 = fmaf(w, f1.y, a3);
                a4 = fmaf(w, f2.x, a4); a5 = fmaf(w, f2.y, a5);
                a6 = fmaf(w, f3.x, a6); a7 = fmaf(w, f3.y, a7);
            }
        }
        __syncwarp();
    }

    // combine 4 groups: round 1 (+6) -> g0+=g1, g2+=g3; round 2 (+12)
#pragma unroll
    for (int d = 6; d <= 12; d += 6) {
        a0 += __shfl_down_sync(0xffffffffu, a0, d);
        a1 += __shfl_down_sync(0xffffffffu, a1, d);
        a2 += __shfl_down_sync(0xffffffffu, a2, d);
        a3 += __shfl_down_sync(0xffffffffu, a3, d);
        a4 += __shfl_down_sync(0xffffffffu, a4, d);
        a5 += __shfl_down_sync(0xffffffffu, a5, d);
        a6 += __shfl_down_sync(0xffffffffu, a6, d);
        a7 += __shfl_down_sync(0xffffffffu, a7, d);
    }

    if (lane < 6) {
        const float4 b0 = ((const float4*)fb)[2 * lane];
        const float4 b1 = ((const float4*)fb)[2 * lane + 1];
        float4 r0, r1;
        r0.x = fmaxf(a0 + b0.x, 0.f); r0.y = fmaxf(a1 + b0.y, 0.f);
        r0.z = fmaxf(a2 + b0.z, 0.f); r0.w = fmaxf(a3 + b0.w, 0.f);
        r1.x = fmaxf(a4 + b1.x, 0.f); r1.y = fmaxf(a5 + b1.y, 0.f);
        r1.z = fmaxf(a6 + b1.z, 0.f); r1.w = fmaxf(a7 + b1.w, 0.f);
        float* op = out + i * OD + lane * 8;
        *(float4*)op       = r0;
        *(float4*)(op + 4) = r1;
    }
}

// ---------------------------------------------------------------------------
extern "C" void kernel_launch(void* const* d_in, const int* in_sizes, int n_in,
                              void* d_out, int out_size) {
    const float* ypred  = (const float*)d_in[0];
    const float* hidden = (const float*)d_in[1];
    const float* fc_w   = (const float*)d_in[2];
    const float* fc_b   = (const float*)d_in[3];
    float* out = (float*)d_out;

    k_reshape<<<(H * PC + 255) / 256, 256>>>(fc_w);
    k_gemmP<<<NA / GR, 256>>>(hidden);
    k_seg<<<NA / 8, 256>>>((const float2*)ypred);
    k_main<<<NA / 8, 256>>>(fc_b, out);
}